// round 14
// baseline (speedup 1.0000x reference)
#include <cuda_runtime.h>
#include <cstdint>

// EdgeBlock fused MLP, TF32 mma.sync. Round 13 = R11 staging + 4x2 warp grid
// with anti-spill discipline (#pragma unroll 1, minimal live set), h via smem.
//  warp (wr,wc): rows wr*32..+32 (2 m-tiles) x cols wc*32..+32 -> B reused 2x.
// x = [edges(32) | nodes[send](32) | nodes[recv](32) | globals[batch](16)]  (K=112)
// h = relu(x @ W1 + b1) (64);  y = h @ W2 + b2 (32)

#define TILE_M 128
#define NTHREADS 256

#define SX_STRIDE 116       // conflict-free fragment LDS (116 mod 32 = 20)
#define SH_STRIDE 68
#define SMEM_FLOATS (TILE_M * SX_STRIDE)   // 14848
#define SMEM_BYTES  (SMEM_FLOATS * 4)      // 59392 -> 3 CTAs/SM

// fragment-packed weights: W1P[(ks*8+nt)*32 + lane] = (b0,b1)
__device__ float2 d_W1P[14 * 8 * 32];
__device__ float2 d_W2P[8 * 4 * 32];

__device__ __forceinline__ float tf32_rna(float x) {
    unsigned u;
    asm("cvt.rna.tf32.f32 %0, %1;" : "=r"(u) : "f"(x));
    return __uint_as_float(u);
}

__device__ __forceinline__ void mma_tf32_16x8x8(float* c, const unsigned* a,
                                                unsigned b0, unsigned b1) {
    asm volatile(
        "mma.sync.aligned.m16n8k8.row.col.f32.tf32.tf32.f32 "
        "{%0,%1,%2,%3}, {%4,%5,%6,%7}, {%8,%9}, {%0,%1,%2,%3};"
        : "+f"(c[0]), "+f"(c[1]), "+f"(c[2]), "+f"(c[3])
        : "r"(a[0]), "r"(a[1]), "r"(a[2]), "r"(a[3]), "r"(b0), "r"(b1));
}

__global__ void prep_weights(const float* __restrict__ W1,
                             const float* __restrict__ W2) {
    int i = blockIdx.x * blockDim.x + threadIdx.x;
    if (i < 14 * 8 * 32) {
        int lane = i & 31, nt = (i >> 5) & 7, ks = i >> 8;
        int g = lane >> 2, c = lane & 3;
        float b0 = W1[(ks * 8 + c) * 64 + nt * 8 + g];
        float b1 = W1[(ks * 8 + c + 4) * 64 + nt * 8 + g];
        d_W1P[i] = make_float2(tf32_rna(b0), tf32_rna(b1));
    }
    if (i < 8 * 4 * 32) {
        int lane = i & 31, nt = (i >> 5) & 3, ks = i >> 7;
        int g = lane >> 2, c = lane & 3;
        float b0 = W2[(ks * 8 + c) * 32 + nt * 8 + g];
        float b1 = W2[(ks * 8 + c + 4) * 32 + nt * 8 + g];
        d_W2P[i] = make_float2(tf32_rna(b0), tf32_rna(b1));
    }
}

__global__ void __launch_bounds__(NTHREADS, 3)
edgeblock_kernel(const float* __restrict__ nodes,
                 const float* __restrict__ edges,
                 const float* __restrict__ graph_globals,
                 const int*   __restrict__ send,
                 const int*   __restrict__ recv,
                 const int*   __restrict__ batch_edges,
                 const float* __restrict__ b1,
                 const float* __restrict__ b2,
                 float*       __restrict__ out) {
    extern __shared__ float sm[];
    float* sX = sm;                      // [128][116] tf32 (aliased by sH)

    const int t     = threadIdx.x;
    const int e0    = blockIdx.x * TILE_M;
    const int lane  = t & 31;
    const int w     = t >> 5;            // warp id 0..7

    // ---- stage x tile: one warp = one full row per step (conflict-free STS) ----
    {
        const int sbase = w * 16;        // staging rows [sbase, sbase+16)
        int idxS = __ldg(send        + e0 + sbase + (lane & 15));
        int idxR = __ldg(recv        + e0 + sbase + (lane & 15));
        int idxB = __ldg(batch_edges + e0 + sbase + (lane & 15));
#pragma unroll
        for (int rr = 0; rr < 16; rr++) {
            int e = sbase + rr;
            float* row = sX + e * SX_STRIDE;
            row[lane] = tf32_rna(edges[(size_t)(e0 + e) * 32 + lane]);
            int ns = __shfl_sync(0xffffffffu, idxS, rr);
            row[32 + lane] = tf32_rna(nodes[(size_t)ns * 32 + lane]);
            int nr = __shfl_sync(0xffffffffu, idxR, rr);
            row[64 + lane] = tf32_rna(nodes[(size_t)nr * 32 + lane]);
        }
#pragma unroll
        for (int rr = 0; rr < 8; rr++) {
            int e  = sbase + rr * 2 + (lane >> 4);
            int gb = __shfl_sync(0xffffffffu, idxB, rr * 2 + (lane >> 4));
            sX[e * SX_STRIDE + 96 + (lane & 15)] =
                tf32_rna(graph_globals[(size_t)gb * 16 + (lane & 15)]);
        }
    }
    __syncthreads();

    // ---- warp grid: wr in 0..3 (row groups of 32), wc in 0..1 (col halves) ----
    const int wr = w & 3;
    const int wc = w >> 2;
    const int g  = lane >> 2;
    const int c  = lane & 3;
    const int R  = wr * 32;              // m-tiles at rows R and R+16

    // ---- layer 1: rows [R,R+32) x cols [wc*32, wc*32+32) ----
    float acc[2][4][4];
#pragma unroll
    for (int mt = 0; mt < 2; mt++)
#pragma unroll
        for (int nl = 0; nl < 4; nl++)
#pragma unroll
            for (int q = 0; q < 4; q++) acc[mt][nl][q] = 0.0f;

#pragma unroll 1
    for (int ks = 0; ks < 14; ks++) {
        const int k = ks * 8;
        float2 b[4];
#pragma unroll
        for (int nl = 0; nl < 4; nl++)
            b[nl] = __ldg(d_W1P + (ks * 8 + wc * 4 + nl) * 32 + lane);
#pragma unroll
        for (int mt = 0; mt < 2; mt++) {
            int r = R + mt * 16 + g;
            unsigned a[4];
            a[0] = __float_as_uint(sX[r * SX_STRIDE + k + c]);
            a[1] = __float_as_uint(sX[(r + 8) * SX_STRIDE + k + c]);
            a[2] = __float_as_uint(sX[r * SX_STRIDE + k + c + 4]);
            a[3] = __float_as_uint(sX[(r + 8) * SX_STRIDE + k + c + 4]);
#pragma unroll
            for (int nl = 0; nl < 4; nl++)
                mma_tf32_16x8x8(acc[mt][nl], a,
                                __float_as_uint(b[nl].x), __float_as_uint(b[nl].y));
        }
    }
    __syncthreads();   // all warps done reading sX; sH aliases it

    // ---- bias + relu + tf32 -> smem h ----
    float* sH = sm;   // [128][68]
#pragma unroll
    for (int mt = 0; mt < 2; mt++) {
        int r = R + mt * 16 + g;
#pragma unroll
        for (int nl = 0; nl < 4; nl++) {
            int col = (wc * 4 + nl) * 8 + 2 * c;
            float bb0 = __ldg(b1 + col), bb1 = __ldg(b1 + col + 1);
            sH[r * SH_STRIDE + col]           = tf32_rna(fmaxf(acc[mt][nl][0] + bb0, 0.0f));
            sH[r * SH_STRIDE + col + 1]       = tf32_rna(fmaxf(acc[mt][nl][1] + bb1, 0.0f));
            sH[(r + 8) * SH_STRIDE + col]     = tf32_rna(fmaxf(acc[mt][nl][2] + bb0, 0.0f));
            sH[(r + 8) * SH_STRIDE + col + 1] = tf32_rna(fmaxf(acc[mt][nl][3] + bb1, 0.0f));
        }
    }
    __syncthreads();

    // ---- layer 2: rows [R,R+32) x cols [wc*16, wc*16+16) ----
    float d2[2][2][4];
#pragma unroll
    for (int mt = 0; mt < 2; mt++)
#pragma unroll
        for (int nl = 0; nl < 2; nl++)
#pragma unroll
            for (int q = 0; q < 4; q++) d2[mt][nl][q] = 0.0f;

#pragma unroll 1
    for (int ks = 0; ks < 8; ks++) {
        const int k = ks * 8;
        float2 b[2];
#pragma unroll
        for (int nl = 0; nl < 2; nl++)
            b[nl] = __ldg(d_W2P + (ks * 4 + wc * 2 + nl) * 32 + lane);
#pragma unroll
        for (int mt = 0; mt < 2; mt++) {
            int r = R + mt * 16 + g;
            unsigned a[4];
            a[0] = __float_as_uint(sH[r * SH_STRIDE + k + c]);
            a[1] = __float_as_uint(sH[(r + 8) * SH_STRIDE + k + c]);
            a[2] = __float_as_uint(sH[r * SH_STRIDE + k + c + 4]);
            a[3] = __float_as_uint(sH[(r + 8) * SH_STRIDE + k + c + 4]);
#pragma unroll
            for (int nl = 0; nl < 2; nl++)
                mma_tf32_16x8x8(d2[mt][nl], a,
                                __float_as_uint(b[nl].x), __float_as_uint(b[nl].y));
        }
    }

    // ---- epilogue: bias + store out[E,32] ----
#pragma unroll
    for (int mt = 0; mt < 2; mt++) {
        int r = R + mt * 16 + g;
#pragma unroll
        for (int nl = 0; nl < 2; nl++) {
            int col = (wc * 2 + nl) * 8 + 2 * c;
            float bb0 = __ldg(b2 + col), bb1 = __ldg(b2 + col + 1);
            float2 v0 = make_float2(d2[mt][nl][0] + bb0, d2[mt][nl][1] + bb1);
            float2 v1 = make_float2(d2[mt][nl][2] + bb0, d2[mt][nl][3] + bb1);
            *reinterpret_cast<float2*>(out + (size_t)(e0 + r) * 32 + col)     = v0;
            *reinterpret_cast<float2*>(out + (size_t)(e0 + r + 8) * 32 + col) = v1;
        }
    }
}

extern "C" void kernel_launch(void* const* d_in, const int* in_sizes, int n_in,
                              void* d_out, int out_size) {
    const float* nodes         = (const float*)d_in[0];
    const float* edges         = (const float*)d_in[1];
    const float* graph_globals = (const float*)d_in[2];
    const int*   send          = (const int*)d_in[3];
    const int*   recv          = (const int*)d_in[4];
    const int*   batch_edges   = (const int*)d_in[5];
    const float* W1            = (const float*)d_in[6];
    const float* b1            = (const float*)d_in[7];
    const float* W2            = (const float*)d_in[8];
    const float* b2            = (const float*)d_in[9];
    float*       out           = (float*)d_out;

    const int n_edges = in_sizes[1] / 32;          // 1,600,000
    const int grid    = (n_edges + TILE_M - 1) / TILE_M;

    prep_weights<<<(14 * 8 * 32 + 255) / 256, 256>>>(W1, W2);

    cudaFuncSetAttribute(edgeblock_kernel,
                         cudaFuncAttributeMaxDynamicSharedMemorySize, SMEM_BYTES);
    edgeblock_kernel<<<grid, NTHREADS, SMEM_BYTES>>>(
        nodes, edges, graph_globals, send, recv, batch_edges,
        b1, b2, out);
}

// round 15
// speedup vs baseline: 1.0601x; 1.0601x over previous
#include <cuda_runtime.h>
#include <cstdint>

// EdgeBlock fused MLP, TF32 mma.sync. Round 15 = R13 (4x2 warp grid, smem h)
// with loop-overhead surgery: hoisted incremental pointers, unroll-2 layer 1,
// fully-unrolled layer 2. Same wavefront ledger as R13, far fewer issued ops.
// x = [edges(32) | nodes[send](32) | nodes[recv](32) | globals[batch](16)]  (K=112)
// h = relu(x @ W1 + b1) (64);  y = h @ W2 + b2 (32)

#define TILE_M 128
#define NTHREADS 256

#define SX_STRIDE 116       // conflict-free fragment LDS (116 mod 32 = 20)
#define SH_STRIDE 68
#define SMEM_FLOATS (TILE_M * SX_STRIDE)   // 14848
#define SMEM_BYTES  (SMEM_FLOATS * 4)      // 59392 -> 3 CTAs/SM

// fragment-packed weights: W1P[(ks*8+nt)*32 + lane] = (b0,b1)
__device__ float2 d_W1P[14 * 8 * 32];
__device__ float2 d_W2P[8 * 4 * 32];

__device__ __forceinline__ float tf32_rna(float x) {
    unsigned u;
    asm("cvt.rna.tf32.f32 %0, %1;" : "=r"(u) : "f"(x));
    return __uint_as_float(u);
}

__device__ __forceinline__ void mma_tf32_16x8x8(float* c, const unsigned* a,
                                                unsigned b0, unsigned b1) {
    asm volatile(
        "mma.sync.aligned.m16n8k8.row.col.f32.tf32.tf32.f32 "
        "{%0,%1,%2,%3}, {%4,%5,%6,%7}, {%8,%9}, {%0,%1,%2,%3};"
        : "+f"(c[0]), "+f"(c[1]), "+f"(c[2]), "+f"(c[3])
        : "r"(a[0]), "r"(a[1]), "r"(a[2]), "r"(a[3]), "r"(b0), "r"(b1));
}

__global__ void prep_weights(const float* __restrict__ W1,
                             const float* __restrict__ W2) {
    int i = blockIdx.x * blockDim.x + threadIdx.x;
    if (i < 14 * 8 * 32) {
        int lane = i & 31, nt = (i >> 5) & 7, ks = i >> 8;
        int g = lane >> 2, c = lane & 3;
        float b0 = W1[(ks * 8 + c) * 64 + nt * 8 + g];
        float b1 = W1[(ks * 8 + c + 4) * 64 + nt * 8 + g];
        d_W1P[i] = make_float2(tf32_rna(b0), tf32_rna(b1));
    }
    if (i < 8 * 4 * 32) {
        int lane = i & 31, nt = (i >> 5) & 3, ks = i >> 7;
        int g = lane >> 2, c = lane & 3;
        float b0 = W2[(ks * 8 + c) * 32 + nt * 8 + g];
        float b1 = W2[(ks * 8 + c + 4) * 32 + nt * 8 + g];
        d_W2P[i] = make_float2(tf32_rna(b0), tf32_rna(b1));
    }
}

__global__ void __launch_bounds__(NTHREADS, 3)
edgeblock_kernel(const float* __restrict__ nodes,
                 const float* __restrict__ edges,
                 const float* __restrict__ graph_globals,
                 const int*   __restrict__ send,
                 const int*   __restrict__ recv,
                 const int*   __restrict__ batch_edges,
                 const float* __restrict__ b1,
                 const float* __restrict__ b2,
                 float*       __restrict__ out) {
    extern __shared__ float sm[];
    float* sX = sm;                      // [128][116] tf32 (aliased by sH)

    const int t     = threadIdx.x;
    const int e0    = blockIdx.x * TILE_M;
    const int lane  = t & 31;
    const int w     = t >> 5;            // warp id 0..7

    // ---- stage x tile: one warp = one full row per step (conflict-free STS) ----
    {
        const int sbase = w * 16;        // staging rows [sbase, sbase+16)
        int idxS = __ldg(send        + e0 + sbase + (lane & 15));
        int idxR = __ldg(recv        + e0 + sbase + (lane & 15));
        int idxB = __ldg(batch_edges + e0 + sbase + (lane & 15));
#pragma unroll
        for (int rr = 0; rr < 16; rr++) {
            int e = sbase + rr;
            float* row = sX + e * SX_STRIDE;
            row[lane] = tf32_rna(edges[(size_t)(e0 + e) * 32 + lane]);
            int ns = __shfl_sync(0xffffffffu, idxS, rr);
            row[32 + lane] = tf32_rna(nodes[(size_t)ns * 32 + lane]);
            int nr = __shfl_sync(0xffffffffu, idxR, rr);
            row[64 + lane] = tf32_rna(nodes[(size_t)nr * 32 + lane]);
        }
#pragma unroll
        for (int rr = 0; rr < 8; rr++) {
            int e  = sbase + rr * 2 + (lane >> 4);
            int gb = __shfl_sync(0xffffffffu, idxB, rr * 2 + (lane >> 4));
            sX[e * SX_STRIDE + 96 + (lane & 15)] =
                tf32_rna(graph_globals[(size_t)gb * 16 + (lane & 15)]);
        }
    }
    __syncthreads();

    // ---- warp grid: wr in 0..3 (row groups of 32), wc in 0..1 (col halves) ----
    const int wr = w & 3;
    const int wc = w >> 2;
    const int g  = lane >> 2;
    const int c  = lane & 3;
    const int R  = wr * 32;              // m-tiles at rows R and R+16

    // ---- layer 1: rows [R,R+32) x cols [wc*32, wc*32+32) ----
    float acc[2][4][4];
#pragma unroll
    for (int mt = 0; mt < 2; mt++)
#pragma unroll
        for (int nl = 0; nl < 4; nl++)
#pragma unroll
            for (int q = 0; q < 4; q++) acc[mt][nl][q] = 0.0f;

    {
        // hoisted incremental pointers
        const float*  pA0 = sX + (R + g) * SX_STRIDE + c;        // [0]:a0  [4]:a2
        const float*  pA1 = pA0 + 8 * SX_STRIDE;                 // [0]:a1  [4]:a3
        const float*  pA2 = pA0 + 16 * SX_STRIDE;                // mt=1
        const float*  pA3 = pA1 + 16 * SX_STRIDE;
        const float2* pB  = d_W1P + (wc * 4) * 32 + lane;        // +32 per nt, +256 per ks

#pragma unroll 2
        for (int ks = 0; ks < 14; ks++) {
            float2 b0 = __ldg(pB);
            float2 b1v = __ldg(pB + 32);
            float2 b2v = __ldg(pB + 64);
            float2 b3 = __ldg(pB + 96);
            unsigned a[4];
            a[0] = __float_as_uint(pA0[0]);
            a[1] = __float_as_uint(pA1[0]);
            a[2] = __float_as_uint(pA0[4]);
            a[3] = __float_as_uint(pA1[4]);
            mma_tf32_16x8x8(acc[0][0], a, __float_as_uint(b0.x),  __float_as_uint(b0.y));
            mma_tf32_16x8x8(acc[0][1], a, __float_as_uint(b1v.x), __float_as_uint(b1v.y));
            mma_tf32_16x8x8(acc[0][2], a, __float_as_uint(b2v.x), __float_as_uint(b2v.y));
            mma_tf32_16x8x8(acc[0][3], a, __float_as_uint(b3.x),  __float_as_uint(b3.y));
            a[0] = __float_as_uint(pA2[0]);
            a[1] = __float_as_uint(pA3[0]);
            a[2] = __float_as_uint(pA2[4]);
            a[3] = __float_as_uint(pA3[4]);
            mma_tf32_16x8x8(acc[1][0], a, __float_as_uint(b0.x),  __float_as_uint(b0.y));
            mma_tf32_16x8x8(acc[1][1], a, __float_as_uint(b1v.x), __float_as_uint(b1v.y));
            mma_tf32_16x8x8(acc[1][2], a, __float_as_uint(b2v.x), __float_as_uint(b2v.y));
            mma_tf32_16x8x8(acc[1][3], a, __float_as_uint(b3.x),  __float_as_uint(b3.y));
            pA0 += 8; pA1 += 8; pA2 += 8; pA3 += 8;
            pB  += 256;
        }
    }
    __syncthreads();   // all warps done reading sX; sH aliases it

    // ---- bias + relu + tf32 -> smem h ----
    float* sH = sm;   // [128][68]
#pragma unroll
    for (int mt = 0; mt < 2; mt++) {
        int r = R + mt * 16 + g;
#pragma unroll
        for (int nl = 0; nl < 4; nl++) {
            int col = (wc * 4 + nl) * 8 + 2 * c;
            float bb0 = __ldg(b1 + col), bb1 = __ldg(b1 + col + 1);
            sH[r * SH_STRIDE + col]           = tf32_rna(fmaxf(acc[mt][nl][0] + bb0, 0.0f));
            sH[r * SH_STRIDE + col + 1]       = tf32_rna(fmaxf(acc[mt][nl][1] + bb1, 0.0f));
            sH[(r + 8) * SH_STRIDE + col]     = tf32_rna(fmaxf(acc[mt][nl][2] + bb0, 0.0f));
            sH[(r + 8) * SH_STRIDE + col + 1] = tf32_rna(fmaxf(acc[mt][nl][3] + bb1, 0.0f));
        }
    }
    __syncthreads();

    // ---- layer 2: rows [R,R+32) x cols [wc*16, wc*16+16) ----
    float d2[2][2][4];
#pragma unroll
    for (int mt = 0; mt < 2; mt++)
#pragma unroll
        for (int nl = 0; nl < 2; nl++)
#pragma unroll
            for (int q = 0; q < 4; q++) d2[mt][nl][q] = 0.0f;

    {
        const float*  pH0 = sH + (R + g) * SH_STRIDE + c;
        const float*  pH1 = pH0 + 8 * SH_STRIDE;
        const float*  pH2 = pH0 + 16 * SH_STRIDE;
        const float*  pH3 = pH1 + 16 * SH_STRIDE;
        const float2* pB2 = d_W2P + (wc * 2) * 32 + lane;        // +32 per nt, +128 per ks

#pragma unroll
        for (int ks = 0; ks < 8; ks++) {
            const int k = ks * 8;
            float2 b0 = __ldg(pB2 + ks * 128);
            float2 b1v = __ldg(pB2 + ks * 128 + 32);
            unsigned a[4];
            a[0] = __float_as_uint(pH0[k]);
            a[1] = __float_as_uint(pH1[k]);
            a[2] = __float_as_uint(pH0[k + 4]);
            a[3] = __float_as_uint(pH1[k + 4]);
            mma_tf32_16x8x8(d2[0][0], a, __float_as_uint(b0.x),  __float_as_uint(b0.y));
            mma_tf32_16x8x8(d2[0][1], a, __float_as_uint(b1v.x), __float_as_uint(b1v.y));
            a[0] = __float_as_uint(pH2[k]);
            a[1] = __float_as_uint(pH3[k]);
            a[2] = __float_as_uint(pH2[k + 4]);
            a[3] = __float_as_uint(pH3[k + 4]);
            mma_tf32_16x8x8(d2[1][0], a, __float_as_uint(b0.x),  __float_as_uint(b0.y));
            mma_tf32_16x8x8(d2[1][1], a, __float_as_uint(b1v.x), __float_as_uint(b1v.y));
        }
    }

    // ---- epilogue: bias + store out[E,32] ----
#pragma unroll
    for (int mt = 0; mt < 2; mt++) {
        int r = R + mt * 16 + g;
#pragma unroll
        for (int nl = 0; nl < 2; nl++) {
            int col = (wc * 2 + nl) * 8 + 2 * c;
            float bb0 = __ldg(b2 + col), bb1 = __ldg(b2 + col + 1);
            float2 v0 = make_float2(d2[mt][nl][0] + bb0, d2[mt][nl][1] + bb1);
            float2 v1 = make_float2(d2[mt][nl][2] + bb0, d2[mt][nl][3] + bb1);
            *reinterpret_cast<float2*>(out + (size_t)(e0 + r) * 32 + col)     = v0;
            *reinterpret_cast<float2*>(out + (size_t)(e0 + r + 8) * 32 + col) = v1;
        }
    }
}

extern "C" void kernel_launch(void* const* d_in, const int* in_sizes, int n_in,
                              void* d_out, int out_size) {
    const float* nodes         = (const float*)d_in[0];
    const float* edges         = (const float*)d_in[1];
    const float* graph_globals = (const float*)d_in[2];
    const int*   send          = (const int*)d_in[3];
    const int*   recv          = (const int*)d_in[4];
    const int*   batch_edges   = (const int*)d_in[5];
    const float* W1            = (const float*)d_in[6];
    const float* b1            = (const float*)d_in[7];
    const float* W2            = (const float*)d_in[8];
    const float* b2            = (const float*)d_in[9];
    float*       out           = (float*)d_out;

    const int n_edges = in_sizes[1] / 32;          // 1,600,000
    const int grid    = (n_edges + TILE_M - 1) / TILE_M;

    prep_weights<<<(14 * 8 * 32 + 255) / 256, 256>>>(W1, W2);

    cudaFuncSetAttribute(edgeblock_kernel,
                         cudaFuncAttributeMaxDynamicSharedMemorySize, SMEM_BYTES);
    edgeblock_kernel<<<grid, NTHREADS, SMEM_BYTES>>>(
        nodes, edges, graph_globals, send, recv, batch_edges,
        b1, b2, out);
}